// round 6
// baseline (speedup 1.0000x reference)
#include <cuda_runtime.h>
#include <cuda_bf16.h>

// RegionSelector: sampling_map [B=128, 1, 512, 512] fp32.
// GRID=4 -> 16 cells of 128x128. WIN=3 -> n=2 -> four 3x3 windows. TOPK=1.
// Output [B, 1, 2] float32 = (row, col) of argmax window.
//
// Kernel 1: 1024 CTAs (8 slices x 128 batches), 256 thr. Each CTA sums a
//   64-row slice (within one row-cell band) into 4 column-cell partials.
//   Every scratch slot is written by exactly one CTA -> deterministic.
// Kernel 2: 1 block x 128 thr. Fold 8 slices -> 16 cell sums, 2x2 window
//   argmax, write (row, col) as floats.

#define B_      128
#define HW      512
#define HW4     (HW / 4)       // 128 float4 per image row
#define NSLICE  8              // slices per batch (2 per row-cell band)
#define SROWS   64             // rows per slice
#define NT1     256

// scratch[b][slice][colcell]
__device__ float g_partial[B_ * NSLICE * 4];

__global__ __launch_bounds__(NT1, 4)
void slice_sum_kernel(const float* __restrict__ in) {
    const int s   = blockIdx.x;          // 0..7  slice within batch
    const int b   = blockIdx.y;          // 0..127
    const int tid = threadIdx.x;

    const float4* __restrict__ base = reinterpret_cast<const float4*>(
        in + (size_t)b * (HW * HW) + (size_t)s * SROWS * HW);

    // c = tid & 127 -> float4 column (0..127); rphase = tid >> 7 (0..1).
    // Thread reads rows r = rphase + 2k, k = 0..31. Warp = 32 consecutive
    // float4 = 512B contiguous; colcell = c>>5 uniform per warp.
    const int c      = tid & 127;
    const int rphase = tid >> 7;
    const int lane   = tid & 31;
    const int wid    = tid >> 5;         // 0..7; colcell = wid & 3

    float sum = 0.f;
    #pragma unroll 8
    for (int k = 0; k < 32; k++) {
        float4 v = __ldcs(base + (size_t)(rphase + 2 * k) * HW4 + c);
        sum += (v.x + v.y) + (v.z + v.w);
    }

    #pragma unroll
    for (int off = 16; off > 0; off >>= 1)
        sum += __shfl_down_sync(0xFFFFFFFFu, sum, off);

    __shared__ float wsum[8];
    if (lane == 0) wsum[wid] = sum;
    __syncthreads();

    // Warps w and w+4 share colcell (w & 3): combine and write one partial.
    if (tid < 4)
        g_partial[(b * NSLICE + s) * 4 + tid] = wsum[tid] + wsum[tid + 4];
}

__global__ __launch_bounds__(128)
void window_argmax_kernel(float* __restrict__ out) {
    const int b = threadIdx.x;
    if (b >= B_) return;

    // cell[rc][cc] = partial[2rc][cc] + partial[2rc+1][cc]
    float cell[16];
    const float* p = g_partial + b * NSLICE * 4;
    #pragma unroll
    for (int rc = 0; rc < 4; rc++)
        #pragma unroll
        for (int cc = 0; cc < 4; cc++)
            cell[rc * 4 + cc] = p[(2 * rc) * 4 + cc] + p[(2 * rc + 1) * 4 + cc];

    // Four 3x3 windows over the 4x4 grid (n = 2). Argmax invariant to the
    // uniform 1/16384 mean scaling. Strict > => lowest index wins ties.
    float best = -3.402823466e+38f;
    int best_idx = 0;
    #pragma unroll
    for (int r = 0; r < 2; r++) {
        #pragma unroll
        for (int cw = 0; cw < 2; cw++) {
            float w = 0.f;
            #pragma unroll
            for (int dr = 0; dr < 3; dr++)
                #pragma unroll
                for (int dc = 0; dc < 3; dc++)
                    w += cell[(r + dr) * 4 + (cw + dc)];
            const int idx = r * 2 + cw;
            if (w > best) { best = w; best_idx = idx; }
        }
    }

    out[b * 2 + 0] = (float)(best_idx >> 1);   // row = idx / n
    out[b * 2 + 1] = (float)(best_idx & 1);    // col = idx % n
}

extern "C" void kernel_launch(void* const* d_in, const int* in_sizes, int n_in,
                              void* d_out, int out_size) {
    const float* in = (const float*)d_in[0];
    float* out = (float*)d_out;

    dim3 grid1(NSLICE, B_);
    slice_sum_kernel<<<grid1, NT1>>>(in);
    window_argmax_kernel<<<1, 128>>>(out);
}

// round 7
// speedup vs baseline: 1.0920x; 1.0920x over previous
#include <cuda_runtime.h>
#include <cuda_bf16.h>

// RegionSelector: sampling_map [B=128, 1, 512, 512] fp32.
// GRID=4 -> 16 cells of 128x128. WIN=3 -> n=2 -> four 3x3 windows. TOPK=1.
// Output [B, 1, 2] float32 = (row, col) of argmax window.
//
// Single launch: 1024 CTAs (8 slices x 128 batches) x 256 thr.
// Each CTA sums a 64-row slice into 4 column-cell partials (unique scratch
// slots -> deterministic). The last CTA to finish for a batch (per-batch
// atomic counter) folds the 32 partials, does the 2x2 window argmax, writes
// the result, and resets the counter (graph-replay idempotent).

#define B_      128
#define HW      512
#define HW4     (HW / 4)       // 128 float4 per image row
#define NSLICE  8
#define SROWS   64
#define NT1     256

__device__ float        g_partial[B_ * NSLICE * 4];  // [b][slice][colcell]
__device__ unsigned int g_count[B_];                 // zero-init; reset after use

__global__ __launch_bounds__(NT1, 4)
void region_selector_kernel(const float* __restrict__ in, float* __restrict__ out) {
    const int s   = blockIdx.x;          // 0..7  slice within batch
    const int b   = blockIdx.y;          // 0..127
    const int tid = threadIdx.x;

    const float4* __restrict__ base = reinterpret_cast<const float4*>(
        in + (size_t)b * (HW * HW) + (size_t)s * SROWS * HW);

    // c = tid & 127 -> float4 column; rphase = tid >> 7 (0..1).
    // Warp = 32 consecutive float4 = 512B contiguous; colcell = wid & 3.
    const int c      = tid & 127;
    const int rphase = tid >> 7;
    const int lane   = tid & 31;
    const int wid    = tid >> 5;         // 0..7

    float sum = 0.f;
    #pragma unroll 8
    for (int k = 0; k < 32; k++) {
        float4 v = __ldcs(base + (size_t)(rphase + 2 * k) * HW4 + c);
        sum += (v.x + v.y) + (v.z + v.w);
    }

    #pragma unroll
    for (int off = 16; off > 0; off >>= 1)
        sum += __shfl_down_sync(0xFFFFFFFFu, sum, off);

    __shared__ float wsum[8];
    __shared__ unsigned int s_last;
    if (lane == 0) wsum[wid] = sum;
    __syncthreads();

    // Warps w and w+4 share colcell: combine, write this slice's 4 partials.
    if (tid < 4)
        g_partial[(b * NSLICE + s) * 4 + tid] = wsum[tid] + wsum[tid + 4];
    __syncthreads();

    // Signal completion; detect last CTA of this batch.
    if (tid == 0) {
        __threadfence();
        s_last = atomicAdd(&g_count[b], 1u);
    }
    __syncthreads();
    if (s_last != NSLICE - 1) return;

    // Last CTA: fold 8x4 partials -> 16 cell sums, 2x2 window argmax.
    if (tid == 0) {
        g_count[b] = 0;                  // reset for next graph replay
        const float* p = g_partial + b * NSLICE * 4;
        float cell[16];
        #pragma unroll
        for (int rc = 0; rc < 4; rc++)
            #pragma unroll
            for (int cc = 0; cc < 4; cc++)
                cell[rc * 4 + cc] = p[(2 * rc) * 4 + cc] + p[(2 * rc + 1) * 4 + cc];

        // Four 3x3 windows over the 4x4 grid (n = 2). Argmax invariant to the
        // uniform 1/16384 mean scaling. Strict > => lowest index wins ties.
        float best = -3.402823466e+38f;
        int best_idx = 0;
        #pragma unroll
        for (int r = 0; r < 2; r++) {
            #pragma unroll
            for (int cw = 0; cw < 2; cw++) {
                float w = 0.f;
                #pragma unroll
                for (int dr = 0; dr < 3; dr++)
                    #pragma unroll
                    for (int dc = 0; dc < 3; dc++)
                        w += cell[(r + dr) * 4 + (cw + dc)];
                const int idx = r * 2 + cw;
                if (w > best) { best = w; best_idx = idx; }
            }
        }
        out[b * 2 + 0] = (float)(best_idx >> 1);   // row = idx / n
        out[b * 2 + 1] = (float)(best_idx & 1);    // col = idx % n
    }
}

extern "C" void kernel_launch(void* const* d_in, const int* in_sizes, int n_in,
                              void* d_out, int out_size) {
    const float* in = (const float*)d_in[0];
    float* out = (float*)d_out;
    dim3 grid(NSLICE, B_);
    region_selector_kernel<<<grid, NT1>>>(in, out);
}